// round 2
// baseline (speedup 1.0000x reference)
#include <cuda_runtime.h>
#include <cuda_bf16.h>

#define HT   256
#define WD   512
#define HWSZ (HT*WD)
#define CIN  64
#define COUT 64
#define KK2  9
#define NTHREADS 512

// packed f32x2 FMA: acc = w*s + acc  (two fp32 FMAs per instruction, sm_103a)
__device__ __forceinline__ void ffma2(unsigned long long &acc,
                                      unsigned long long w,
                                      unsigned long long s) {
    asm("fma.rn.f32x2 %0, %1, %2, %0;" : "+l"(acc) : "l"(w), "l"(s));
}

__global__ __launch_bounds__(NTHREADS, 1)
void sphere_conv_kernel(const float* __restrict__ x,
                        const float* __restrict__ wgt,
                        const float* __restrict__ pos,
                        float* __restrict__ out) {
    extern __shared__ float sw[];   // wT[k][c][o] : 9*64*64 floats = 147456 B

    // cooperative transposed weight load: weight[o][c][k] -> sw[(k*CIN+c)*COUT+o]
    for (int idx = threadIdx.x; idx < COUT * CIN * KK2; idx += NTHREADS) {
        int o  = idx / (CIN * KK2);
        int r  = idx % (CIN * KK2);
        int c  = r / KK2;
        int kk = r % KK2;
        sw[(kk * CIN + c) * COUT + o] = wgt[idx];
    }
    __syncthreads();

    const int row = blockIdx.x;     // 0..511 : n*HT + h
    const int n   = row >> 8;
    const int h   = row & (HT - 1);
    const int w   = threadIdx.x;    // 0..511
    const int hw  = h * WD + w;

    const float* xn = x + (size_t)n * CIN * HWSZ;

    unsigned long long acc[COUT / 2];
#pragma unroll
    for (int i = 0; i < COUT / 2; i++) acc[i] = 0ULL;   // packed {0.f,0.f}

#pragma unroll 1
    for (int kk = 0; kk < KK2; kk++) {
        const float py = pos[(size_t)(2 * kk)     * HWSZ + hw];
        const float px = pos[(size_t)(2 * kk + 1) * HWSZ + hw];

        const float y0f = floorf(py);
        const float x0f = floorf(px);
        const float dy  = py - y0f;
        const float dx  = px - x0f;
        const float y1f = y0f + 1.0f;
        const float x1f = x0f + 1.0f;

        const float vy0 = (y0f >= 0.0f && y0f <= (float)(HT - 1)) ? 1.0f : 0.0f;
        const float vy1 = (y1f >= 0.0f && y1f <= (float)(HT - 1)) ? 1.0f : 0.0f;
        const float vx0 = (x0f >= 0.0f && x0f <= (float)(WD - 1)) ? 1.0f : 0.0f;
        const float vx1 = (x1f >= 0.0f && x1f <= (float)(WD - 1)) ? 1.0f : 0.0f;

        const float w00 = (1.0f - dy) * (1.0f - dx) * vy0 * vx0;
        const float w01 = (1.0f - dy) * dx          * vy0 * vx1;
        const float w10 = dy          * (1.0f - dx) * vy1 * vx0;
        const float w11 = dy          * dx          * vy1 * vx1;

        const int yi0 = min(max((int)y0f, 0), HT - 1);
        const int yi1 = min(max((int)y1f, 0), HT - 1);
        const int xi0 = min(max((int)x0f, 0), WD - 1);
        const int xi1 = min(max((int)x1f, 0), WD - 1);

        const int o00 = yi0 * WD + xi0;
        const int o01 = yi0 * WD + xi1;
        const int o10 = yi1 * WD + xi0;
        const int o11 = yi1 * WD + xi1;

        // software-pipelined gather over input channels
        float a0 = xn[o00], a1 = xn[o01], a2 = xn[o10], a3 = xn[o11];

#pragma unroll 1
        for (int c = 0; c < CIN; c++) {
            // prefetch next channel's corners (clamped: last iter re-reads c=63)
            const float* np = xn + (size_t)min(c + 1, CIN - 1) * HWSZ;
            float b0 = np[o00], b1 = np[o01], b2 = np[o10], b3 = np[o11];

            float s = fmaf(w00, a0, fmaf(w01, a1, fmaf(w10, a2, w11 * a3)));

            unsigned long long s2;
            asm("mov.b64 %0, {%1, %1};" : "=l"(s2) : "f"(s));

            const ulonglong2* wr =
                (const ulonglong2*)&sw[(kk * CIN + c) * COUT];
#pragma unroll
            for (int i = 0; i < 16; i++) {
                ulonglong2 wp = wr[i];             // LDS.128 broadcast
                ffma2(acc[2 * i],     wp.x, s2);   // couts 4i, 4i+1
                ffma2(acc[2 * i + 1], wp.y, s2);   // couts 4i+2, 4i+3
            }

            a0 = b0; a1 = b1; a2 = b2; a3 = b3;
        }
    }

    // write out: out[n][o][h][w], o pairs packed in acc[j] -> couts (2j, 2j+1)
    float* op = out + (size_t)n * COUT * HWSZ + hw;
#pragma unroll
    for (int j = 0; j < COUT / 2; j++) {
        float lo, hi;
        asm("mov.b64 {%0, %1}, %2;" : "=f"(lo), "=f"(hi) : "l"(acc[j]));
        op[(size_t)(2 * j)     * HWSZ] = lo;
        op[(size_t)(2 * j + 1) * HWSZ] = hi;
    }
}

extern "C" void kernel_launch(void* const* d_in, const int* in_sizes, int n_in,
                              void* d_out, int out_size) {
    const float* x   = (const float*)d_in[0];
    const float* wgt = (const float*)d_in[1];
    const float* pos = (const float*)d_in[2];
    float* out = (float*)d_out;

    const int smem = COUT * CIN * KK2 * (int)sizeof(float);  // 147456 B
    cudaFuncSetAttribute(sphere_conv_kernel,
                         cudaFuncAttributeMaxDynamicSharedMemorySize, smem);

    sphere_conv_kernel<<<2 * HT, NTHREADS, smem>>>(x, wgt, pos, out);
}

// round 3
// speedup vs baseline: 1.5796x; 1.5796x over previous
#include <cuda_runtime.h>
#include <cuda_bf16.h>

#define HT    256
#define WD    512
#define HWSZ  (HT*WD)          // 131072 = 2^17
#define CIN   64
#define COUT  64
#define KK2   9
#define SP    132              // S row stride (floats): conflict-free staging
#define WSEC  520              // Ws cout-group section stride (floats)

// ---------------- device scratch (static allocation is allowed) -------------
__device__ float  g_xhwc[2u * HT * WD * CIN];     // x in NHWC, 67.1 MB
__device__ float  g_wT[KK2 * CIN * COUT];         // weights [k][cin][cout]
__device__ int4   g_off[KK2 * HWSZ];              // 4 corner word-offsets (NHWC)
__device__ float4 g_wt4[KK2 * HWSZ];              // 4 bilinear weights (masked)

// ---------------- packed fp32x2 helpers -------------------------------------
__device__ __forceinline__ void ffma2(unsigned long long &acc,
                                      unsigned long long w,
                                      unsigned long long s) {
    asm("fma.rn.f32x2 %0, %1, %2, %0;" : "+l"(acc) : "l"(w), "l"(s));
}
__device__ __forceinline__ unsigned long long pack2(float v) {
    unsigned long long r;
    asm("mov.b64 %0, {%1, %1};" : "=l"(r) : "f"(v));
    return r;
}
__device__ __forceinline__ float unpack2(unsigned long long v, int hi) {
    float a, b;
    asm("mov.b64 {%0, %1}, %2;" : "=f"(a), "=f"(b) : "l"(v));
    return hi ? b : a;
}

// ---------------- prep kernel 1: NCHW -> NHWC transpose ---------------------
__global__ void transpose_x(const float* __restrict__ x) {
    __shared__ float tile[32][33];
    const int w0 = blockIdx.x * 32;
    const int c0 = blockIdx.y * 32;
    const int nh = blockIdx.z;            // n*HT + h
    const int n  = nh >> 8;
    const int h  = nh & (HT - 1);

    const float* src = x + ((size_t)(n * CIN + c0)) * HWSZ + h * WD + w0;
#pragma unroll
    for (int i = 0; i < 32; i += 8)
        tile[threadIdx.y + i][threadIdx.x] =
            src[(size_t)(threadIdx.y + i) * HWSZ + threadIdx.x];
    __syncthreads();

    float* dst = g_xhwc + ((size_t)nh * WD + w0) * CIN + c0;
#pragma unroll
    for (int i = 0; i < 32; i += 8)
        dst[(size_t)(threadIdx.y + i) * CIN + threadIdx.x] =
            tile[threadIdx.x][threadIdx.y + i];
}

// ---------------- prep kernel 2: weight transpose ---------------------------
__global__ void transpose_w(const float* __restrict__ wgt) {
    int idx = blockIdx.x * 256 + threadIdx.x;     // (kk*64+cin)*64+cout
    if (idx >= KK2 * CIN * COUT) return;
    int cout = idx & 63;
    int rest = idx >> 6;
    int cin  = rest & 63;
    int kk   = rest >> 6;
    g_wT[idx] = wgt[(cout * CIN + cin) * KK2 + kk];
}

// ---------------- prep kernel 3: bilinear offsets + weights -----------------
__global__ void precomp(const float* __restrict__ pos) {
    int hw = blockIdx.x * 256 + threadIdx.x;      // 0..HWSZ-1
#pragma unroll 1
    for (int tap = 0; tap < KK2; tap++) {
        const float py = pos[(size_t)(2 * tap)     * HWSZ + hw];
        const float px = pos[(size_t)(2 * tap + 1) * HWSZ + hw];
        const float y0f = floorf(py);
        const float x0f = floorf(px);
        const float dy  = py - y0f;
        const float dx  = px - x0f;
        const float y1f = y0f + 1.0f;
        const float x1f = x0f + 1.0f;

        const float vy0 = (y0f >= 0.0f && y0f <= (float)(HT - 1)) ? 1.0f : 0.0f;
        const float vy1 = (y1f >= 0.0f && y1f <= (float)(HT - 1)) ? 1.0f : 0.0f;
        const float vx0 = (x0f >= 0.0f && x0f <= (float)(WD - 1)) ? 1.0f : 0.0f;
        const float vx1 = (x1f >= 0.0f && x1f <= (float)(WD - 1)) ? 1.0f : 0.0f;

        float4 wt;
        wt.x = (1.0f - dy) * (1.0f - dx) * vy0 * vx0;
        wt.y = (1.0f - dy) * dx          * vy0 * vx1;
        wt.z = dy          * (1.0f - dx) * vy1 * vx0;
        wt.w = dy          * dx          * vy1 * vx1;

        const int yi0 = min(max((int)y0f, 0), HT - 1);
        const int yi1 = min(max((int)y1f, 0), HT - 1);
        const int xi0 = min(max((int)x0f, 0), WD - 1);
        const int xi1 = min(max((int)x1f, 0), WD - 1);

        int4 off;
        off.x = (yi0 * WD + xi0) * CIN;
        off.y = (yi0 * WD + xi1) * CIN;
        off.z = (yi1 * WD + xi0) * CIN;
        off.w = (yi1 * WD + xi1) * CIN;

        g_off[tap * HWSZ + hw] = off;
        g_wt4[tap * HWSZ + hw] = wt;
    }
}

// ---------------- main kernel: staged gather + 2D-tiled fp32 GEMM -----------
// block: 128 threads, tile = 128 pixels x 64 couts
// thread (GEMM role): cg = t&3 (16 couts), pg = t>>2 (4 consecutive pixels)
// thread (gather role): wid = t>>5, lane = t&31 (chunk channel)
__global__ __launch_bounds__(128, 4)
void sphere_main(float* __restrict__ out) {
    __shared__ float  S[32 * SP];        // samples [c][pix], pad 132
    __shared__ float  Ws[4 * WSEC];      // weights: 4 cout-group sections
    __shared__ int4   Po[128];
    __shared__ float4 Pw[128];

    const int t       = threadIdx.x;
    const int pixbase = blockIdx.x << 7;          // 128 pixels per block
    const int n       = pixbase >> 17;            // HWSZ = 2^17
    const int hwb     = pixbase & (HWSZ - 1);

    const float* __restrict__ xb = g_xhwc + (size_t)n * (HWSZ * CIN);

    const int wid  = t >> 5, lane = t & 31;       // gather mapping
    const int cg   = t & 3,  pg   = t >> 2;       // GEMM mapping

    unsigned long long acc[4][8];
#pragma unroll
    for (int p = 0; p < 4; p++)
#pragma unroll
        for (int j = 0; j < 8; j++) acc[p][j] = 0ULL;

#pragma unroll 1
    for (int tap = 0; tap < KK2; tap++) {
        // stage per-pixel corner offsets + weights (coalesced int4/float4)
        Po[t] = g_off[tap * HWSZ + hwb + t];
        Pw[t] = g_wt4[tap * HWSZ + hwb + t];
        __syncthreads();

#pragma unroll 1
        for (int half = 0; half < 2; half++) {
            const int c0 = half << 5;

            // ---- stage weight chunk: Ws[cg][c][m] (section stride WSEC) ----
#pragma unroll
            for (int r = 0; r < 16; r++) {
                int idx = t + (r << 7);           // 0..2047
                int c   = idx >> 6;
                int co  = idx & 63;
                Ws[(co >> 4) * WSEC + c * 16 + (co & 15)] =
                    g_wT[(tap * CIN + c0 + c) * COUT + co];
            }

            // ---- gather phase: lane = channel, dense 128B corner loads ----
            const float* __restrict__ bp = xb + c0 + lane;
#pragma unroll 1
            for (int p4 = 0; p4 < 8; p4++) {
                float sv0, sv1, sv2, sv3;
                {
                    const int p = (wid << 5) + (p4 << 2);
                    int4 o0 = Po[p + 0]; float4 q0 = Pw[p + 0];
                    int4 o1 = Po[p + 1]; float4 q1 = Pw[p + 1];
                    int4 o2 = Po[p + 2]; float4 q2 = Pw[p + 2];
                    int4 o3 = Po[p + 3]; float4 q3 = Pw[p + 3];
                    float a00 = bp[o0.x], a01 = bp[o0.y], a02 = bp[o0.z], a03 = bp[o0.w];
                    float a10 = bp[o1.x], a11 = bp[o1.y], a12 = bp[o1.z], a13 = bp[o1.w];
                    float a20 = bp[o2.x], a21 = bp[o2.y], a22 = bp[o2.z], a23 = bp[o2.w];
                    float a30 = bp[o3.x], a31 = bp[o3.y], a32 = bp[o3.z], a33 = bp[o3.w];
                    sv0 = fmaf(q0.x, a00, fmaf(q0.y, a01, fmaf(q0.z, a02, q0.w * a03)));
                    sv1 = fmaf(q1.x, a10, fmaf(q1.y, a11, fmaf(q1.z, a12, q1.w * a13)));
                    sv2 = fmaf(q2.x, a20, fmaf(q2.y, a21, fmaf(q2.z, a22, q2.w * a23)));
                    sv3 = fmaf(q3.x, a30, fmaf(q3.y, a31, fmaf(q3.z, a32, q3.w * a33)));
                }
                *(float4*)&S[lane * SP + (wid << 5) + (p4 << 2)] =
                    make_float4(sv0, sv1, sv2, sv3);
            }
            __syncthreads();

            // ---- GEMM phase: 4 pix x 16 couts per thread -------------------
#pragma unroll 2
            for (int c = 0; c < 32; c++) {
                float4 s4 = *(const float4*)&S[c * SP + (pg << 2)];
                const ulonglong2* wr =
                    (const ulonglong2*)&Ws[cg * WSEC + c * 16];
                ulonglong2 wa = wr[0];
                ulonglong2 wb = wr[1];
                unsigned long long s20 = pack2(s4.x);
                unsigned long long s21 = pack2(s4.y);
                unsigned long long s22 = pack2(s4.z);
                unsigned long long s23 = pack2(s4.w);

                ffma2(acc[0][0], wa.x, s20); ffma2(acc[0][1], wa.y, s20);
                ffma2(acc[0][2], wb.x, s20); ffma2(acc[0][3], wb.y, s20);
                ffma2(acc[1][0], wa.x, s21); ffma2(acc[1][1], wa.y, s21);
                ffma2(acc[1][2], wb.x, s21); ffma2(acc[1][3], wb.y, s21);
                ffma2(acc[2][0], wa.x, s22); ffma2(acc[2][1], wa.y, s22);
                ffma2(acc[2][2], wb.x, s22); ffma2(acc[2][3], wb.y, s22);
                ffma2(acc[3][0], wa.x, s23); ffma2(acc[3][1], wa.y, s23);
                ffma2(acc[3][2], wb.x, s23); ffma2(acc[3][3], wb.y, s23);

                ulonglong2 wc = wr[2];
                ulonglong2 wd = wr[3];
                ffma2(acc[0][4], wc.x, s20); ffma2(acc[0][5], wc.y, s20);
                ffma2(acc[0][6], wd.x, s20); ffma2(acc[0][7], wd.y, s20);
                ffma2(acc[1][4], wc.x, s21); ffma2(acc[1][5], wc.y, s21);
                ffma2(acc[1][6], wd.x, s21); ffma2(acc[1][7], wd.y, s21);
                ffma2(acc[2][4], wc.x, s22); ffma2(acc[2][5], wc.y, s22);
                ffma2(acc[2][6], wd.x, s22); ffma2(acc[2][7], wd.y, s22);
                ffma2(acc[3][4], wc.x, s23); ffma2(acc[3][5], wc.y, s23);
                ffma2(acc[3][6], wd.x, s23); ffma2(acc[3][7], wd.y, s23);
            }
            __syncthreads();
        }
    }

    // ---- epilogue: 16 couts x 4 consecutive pixels per thread --------------
    float* ob = out + (size_t)n * COUT * HWSZ + hwb + (pg << 2);
#pragma unroll
    for (int cc = 0; cc < 16; cc++) {
        const int j  = cc >> 1;
        const int hi = cc & 1;
        float4 v;
        v.x = unpack2(acc[0][j], hi);
        v.y = unpack2(acc[1][j], hi);
        v.z = unpack2(acc[2][j], hi);
        v.w = unpack2(acc[3][j], hi);
        *(float4*)&ob[(size_t)(cg * 16 + cc) * HWSZ] = v;
    }
}

// ---------------- launch ----------------------------------------------------
extern "C" void kernel_launch(void* const* d_in, const int* in_sizes, int n_in,
                              void* d_out, int out_size) {
    const float* x   = (const float*)d_in[0];
    const float* wgt = (const float*)d_in[1];
    const float* pos = (const float*)d_in[2];
    float* out = (float*)d_out;

    transpose_x<<<dim3(WD / 32, CIN / 32, 2 * HT), dim3(32, 8)>>>(x);
    transpose_w<<<(KK2 * CIN * COUT + 255) / 256, 256>>>(wgt);
    precomp<<<HWSZ / 256, 256>>>(pos);
    sphere_main<<<(2 * HWSZ) / 128, 128>>>(out);
}

// round 7
// speedup vs baseline: 1.8516x; 1.1722x over previous
#include <cuda_runtime.h>
#include <cuda_bf16.h>
#include <cstdint>

#define HT    256
#define WD    512
#define HWSZ  (HT*WD)          // 131072
#define CIN   64
#define COUT  64
#define KK2   9
#define KP    256              // K' = 256 (4-term bf16 split)
#define ROWB  512              // bytes per A/B row (KP * 2)

// ---------------- device scratch --------------------------------------------
__device__ float g_xhwc[2u * HT * WD * CIN];            // x in NHWC
__device__ __align__(16) uint16_t g_wB[KK2 * COUT * KP]; // bf16 B' [tap][n][256]
__device__ int4   g_off[KK2 * HWSZ];
__device__ float4 g_wt4[KK2 * HWSZ];

// ---------------- smem layout (bytes) ---------------------------------------
#define OFF_A   0
#define A_BYTES (128 * ROWB)          // 65536
#define OFF_B   A_BYTES
#define B_BYTES (64 * ROWB)           // 32768
#define OFF_PO  (OFF_B + B_BYTES)     // 98304
#define OFF_PW  (OFF_PO + 2048)
#define SMEM_SZ (OFF_PW + 2048)       // 102400

// 16B-chunk swizzle within groups of 8 chunks (rows stride 512 = 0 mod 128)
__device__ __forceinline__ uint32_t swzc(uint32_t c, uint32_t r) {
    return (c & 24u) | ((c ^ r) & 7u);
}
__device__ __forceinline__ uint16_t f2bf(float f) {
    uint16_t r; asm("cvt.rn.bf16.f32 %0, %1;" : "=h"(r) : "f"(f)); return r;
}
__device__ __forceinline__ float bf2f(uint16_t b) {
    return __uint_as_float((uint32_t)b << 16);
}
__device__ __forceinline__ uint32_t smem_u32(const void* p) {
    uint32_t a;
    asm("{ .reg .u64 t; cvta.to.shared.u64 t, %1; cvt.u32.u64 %0, t; }" : "=r"(a) : "l"(p));
    return a;
}
__device__ __forceinline__ void ldsm4(uint32_t r[4], uint32_t addr) {
    asm volatile("ldmatrix.sync.aligned.m8n8.x4.shared.b16 {%0,%1,%2,%3}, [%4];"
                 : "=r"(r[0]), "=r"(r[1]), "=r"(r[2]), "=r"(r[3]) : "r"(addr));
}
__device__ __forceinline__ void mma_bf16(float c[4], const uint32_t a[4],
                                         const uint32_t b[2]) {
    asm volatile("mma.sync.aligned.m16n8k16.row.col.f32.bf16.bf16.f32 "
                 "{%0,%1,%2,%3}, {%4,%5,%6,%7}, {%8,%9}, {%0,%1,%2,%3};"
                 : "+f"(c[0]), "+f"(c[1]), "+f"(c[2]), "+f"(c[3])
                 : "r"(a[0]), "r"(a[1]), "r"(a[2]), "r"(a[3]), "r"(b[0]), "r"(b[1]));
}

// ---------------- prep: NCHW -> NHWC ----------------------------------------
__global__ void transpose_x(const float* __restrict__ x) {
    __shared__ float tile[32][33];
    const int w0 = blockIdx.x * 32, c0 = blockIdx.y * 32, nh = blockIdx.z;
    const int n = nh >> 8, h = nh & (HT - 1);
    const float* src = x + ((size_t)(n * CIN + c0)) * HWSZ + h * WD + w0;
#pragma unroll
    for (int i = 0; i < 32; i += 8)
        tile[threadIdx.y + i][threadIdx.x] = src[(size_t)(threadIdx.y + i) * HWSZ + threadIdx.x];
    __syncthreads();
    float* dst = g_xhwc + ((size_t)nh * WD + w0) * CIN + c0;
#pragma unroll
    for (int i = 0; i < 32; i += 8)
        dst[(size_t)(threadIdx.y + i) * CIN + threadIdx.x] = tile[threadIdx.x][threadIdx.y + i];
}

// ---------------- prep: weight bf16 hi/lo layout -----------------------------
// B'[n][2c]=w_hi, B'[n][2c+1]=w_hi (k<128);  B'[n][128+2c]=B'[n][128+2c+1]=w_lo
__global__ void weight_prep(const float* __restrict__ wgt) {
    int idx = blockIdx.x * 256 + threadIdx.x;    // tap*4096 + nn*64 + c
    if (idx >= KK2 * COUT * CIN) return;
    int c = idx & 63, rest = idx >> 6, nn = rest & 63, tap = rest >> 6;
    float wv = wgt[(nn * CIN + c) * KK2 + tap];
    uint16_t h = f2bf(wv);
    uint16_t l = f2bf(wv - bf2f(h));
    uint16_t* dst = g_wB + ((size_t)tap * COUT + nn) * KP;
    dst[2 * c]           = h;
    dst[2 * c + 1]       = h;
    dst[128 + 2 * c]     = l;
    dst[128 + 2 * c + 1] = l;
}

// ---------------- prep: bilinear offsets + weights --------------------------
__global__ void precomp(const float* __restrict__ pos) {
    int hw = blockIdx.x * 256 + threadIdx.x;
#pragma unroll 1
    for (int tap = 0; tap < KK2; tap++) {
        const float py = pos[(size_t)(2 * tap) * HWSZ + hw];
        const float px = pos[(size_t)(2 * tap + 1) * HWSZ + hw];
        const float y0f = floorf(py), x0f = floorf(px);
        const float dy = py - y0f, dx = px - x0f;
        const float y1f = y0f + 1.0f, x1f = x0f + 1.0f;
        const float vy0 = (y0f >= 0.0f && y0f <= (float)(HT - 1)) ? 1.0f : 0.0f;
        const float vy1 = (y1f >= 0.0f && y1f <= (float)(HT - 1)) ? 1.0f : 0.0f;
        const float vx0 = (x0f >= 0.0f && x0f <= (float)(WD - 1)) ? 1.0f : 0.0f;
        const float vx1 = (x1f >= 0.0f && x1f <= (float)(WD - 1)) ? 1.0f : 0.0f;
        float4 wt;
        wt.x = (1.0f - dy) * (1.0f - dx) * vy0 * vx0;
        wt.y = (1.0f - dy) * dx          * vy0 * vx1;
        wt.z = dy * (1.0f - dx)          * vy1 * vx0;
        wt.w = dy * dx                   * vy1 * vx1;
        const int yi0 = min(max((int)y0f, 0), HT - 1);
        const int yi1 = min(max((int)y1f, 0), HT - 1);
        const int xi0 = min(max((int)x0f, 0), WD - 1);
        const int xi1 = min(max((int)x1f, 0), WD - 1);
        int4 off;
        off.x = (yi0 * WD + xi0) * CIN;
        off.y = (yi0 * WD + xi1) * CIN;
        off.z = (yi1 * WD + xi0) * CIN;
        off.w = (yi1 * WD + xi1) * CIN;
        g_off[tap * HWSZ + hw] = off;
        g_wt4[tap * HWSZ + hw] = wt;
    }
}

// ---------------- main: gather + bf16x4 mma.sync GEMM -----------------------
// block = 128 threads (4 warps), tile = 128 pixels x 64 couts, grid 2048
// warp w: gathers + owns pixels [w*32, w*32+32); mma M=32, N=64, K'=256
__global__ __launch_bounds__(128, 2)
void sphere_mma(float* __restrict__ out) {
    extern __shared__ char smem[];
    const uint32_t sb = smem_u32(smem);
    const int t = threadIdx.x, w = t >> 5, lane = t & 31;

    const int pixbase = blockIdx.x << 7;         // 128 pixels per block
    const int n   = pixbase >> 17;
    const int hwb = pixbase & (HWSZ - 1);
    const float* __restrict__ xb = g_xhwc + (size_t)n * (HWSZ * CIN);

    int4*   Po = (int4*)(smem + OFF_PO);
    float4* Pw = (float4*)(smem + OFF_PW);

    float acc[2][8][4];
#pragma unroll
    for (int mt = 0; mt < 2; mt++)
#pragma unroll
        for (int nt = 0; nt < 8; nt++)
#pragma unroll
            for (int j = 0; j < 4; j++) acc[mt][nt][j] = 0.0f;

    const uint32_t intra = (lane & 3) * 4;

#pragma unroll 1
    for (int tap = 0; tap < KK2; tap++) {
        __syncthreads();   // previous tap's mma done reading B

        // ---- stage B' (64 x 512B, swizzled): 16 x 16B chunks per thread ----
        {
            const char* wsrc = (const char*)(g_wB + (size_t)tap * COUT * KP);
#pragma unroll
            for (int i = 0; i < 16; i++) {
                int id  = t + (i << 7);          // 0..2047
                int row = id >> 5, c = id & 31;
                uint4 v = *(const uint4*)(wsrc + row * ROWB + c * 16);
                *(uint4*)(smem + OFF_B + row * ROWB + swzc(c, row) * 16) = v;
            }
        }

        // ---- stage this warp's Po/Pw -----------------------------------
        Po[w * 32 + lane] = g_off[tap * HWSZ + hwb + w * 32 + lane];
        Pw[w * 32 + lane] = g_wt4[tap * HWSZ + hwb + w * 32 + lane];
        __syncwarp();

        // ---- gather own 32 pixels: lane = channel (ci=lane, lane+32) ----
        const float* bp0 = xb + lane;
        const float* bp1 = xb + 32 + lane;
#pragma unroll 2
        for (int g = 0; g < 8; g++) {
            const int p0 = w * 32 + g * 4;
            int4   o[4];
            float4 q[4];
#pragma unroll
            for (int j = 0; j < 4; j++) { o[j] = Po[p0 + j]; q[j] = Pw[p0 + j]; }

            float A0[4][4], A1[4][4];
#pragma unroll
            for (int j = 0; j < 4; j++) {
                A0[j][0] = bp0[o[j].x]; A0[j][1] = bp0[o[j].y];
                A0[j][2] = bp0[o[j].z]; A0[j][3] = bp0[o[j].w];
                A1[j][0] = bp1[o[j].x]; A1[j][1] = bp1[o[j].y];
                A1[j][2] = bp1[o[j].z]; A1[j][3] = bp1[o[j].w];
            }
#pragma unroll
            for (int j = 0; j < 4; j++) {
                const int pl = p0 + j;
                const uint32_t rb = (uint32_t)pl * ROWB;
                float s0 = fmaf(q[j].x, A0[j][0], fmaf(q[j].y, A0[j][1],
                          fmaf(q[j].z, A0[j][2], q[j].w * A0[j][3])));
                float s1 = fmaf(q[j].x, A1[j][0], fmaf(q[j].y, A1[j][1],
                          fmaf(q[j].z, A1[j][2], q[j].w * A1[j][3])));
                uint16_t h0 = f2bf(s0);
                uint16_t l0 = f2bf(s0 - bf2f(h0));
                uint16_t h1 = f2bf(s1);
                uint16_t l1 = f2bf(s1 - bf2f(h1));
                uint32_t pr0 = (uint32_t)h0 | ((uint32_t)l0 << 16);
                uint32_t pr1 = (uint32_t)h1 | ((uint32_t)l1 << 16);
                // ci = lane: chunks lane>>2 (w_hi region) and 16+(lane>>2) (w_lo region)
                *(uint32_t*)(smem + rb + swzc(lane >> 2, pl) * 16 + intra)        = pr0;
                *(uint32_t*)(smem + rb + swzc(16 + (lane >> 2), pl) * 16 + intra) = pr0;
                // ci = lane+32: chunks 8+(lane>>2) and 24+(lane>>2)
                *(uint32_t*)(smem + rb + swzc(8 + (lane >> 2), pl) * 16 + intra)  = pr1;
                *(uint32_t*)(smem + rb + swzc(24 + (lane >> 2), pl) * 16 + intra) = pr1;
            }
        }
        __syncwarp();
        __syncthreads();   // B' staged (A rows are warp-private)

        // ---- mma: M=32 (this warp's rows), N=64, K'=256 -----------------
        const uint32_t abase = sb + OFF_A;
        const uint32_t bbase = sb + OFF_B;
#pragma unroll 4
        for (int kc = 0; kc < 16; kc++) {
            uint32_t a[2][4];
#pragma unroll
            for (int mt = 0; mt < 2; mt++) {
                uint32_t row = (uint32_t)(w * 32 + mt * 16 + (lane & 15));
                uint32_t kch = (uint32_t)(kc * 2 + (lane >> 4));
                ldsm4(a[mt], abase + row * ROWB + swzc(kch, row) * 16);
            }
            uint32_t b[8][2];
#pragma unroll
            for (int np = 0; np < 4; np++) {
                uint32_t nr  = (uint32_t)(np * 16 + (lane & 7) + ((lane >> 4) << 3));
                uint32_t kch = (uint32_t)(kc * 2 + ((lane >> 3) & 1));
                uint32_t r[4];
                // B stored [n][k]: plain (non-trans) ldmatrix yields the
                // col-major B fragment (lane t -> n=t/4, k=2(t%4)+0/1)
                ldsm4(r, bbase + nr * ROWB + swzc(kch, nr) * 16);
                b[2 * np][0]     = r[0]; b[2 * np][1]     = r[1];
                b[2 * np + 1][0] = r[2]; b[2 * np + 1][1] = r[3];
            }
#pragma unroll
            for (int mt = 0; mt < 2; mt++)
#pragma unroll
                for (int nt = 0; nt < 8; nt++)
                    mma_bf16(acc[mt][nt], a[mt], b[nt]);
        }
    }

    // ---- epilogue ----------------------------------------------------------
    float* ob = out + (size_t)n * COUT * HWSZ + hwb;
#pragma unroll
    for (int mt = 0; mt < 2; mt++) {
        const int pl = w * 32 + mt * 16 + (lane >> 2);
#pragma unroll
        for (int nt = 0; nt < 8; nt++) {
            const int co = nt * 8 + (lane & 3) * 2;
            ob[(size_t)co * HWSZ + pl]           = acc[mt][nt][0];
            ob[(size_t)(co + 1) * HWSZ + pl]     = acc[mt][nt][1];
            ob[(size_t)co * HWSZ + pl + 8]       = acc[mt][nt][2];
            ob[(size_t)(co + 1) * HWSZ + pl + 8] = acc[mt][nt][3];
        }
    }
}

// ---------------- launch ----------------------------------------------------
extern "C" void kernel_launch(void* const* d_in, const int* in_sizes, int n_in,
                              void* d_out, int out_size) {
    const float* x   = (const float*)d_in[0];
    const float* wgt = (const float*)d_in[1];
    const float* pos = (const float*)d_in[2];
    float* out = (float*)d_out;

    transpose_x<<<dim3(WD / 32, CIN / 32, 2 * HT), dim3(32, 8)>>>(x);
    weight_prep<<<(KK2 * COUT * CIN + 255) / 256, 256>>>(wgt);
    precomp<<<HWSZ / 256, 256>>>(pos);

    cudaFuncSetAttribute(sphere_mma, cudaFuncAttributeMaxDynamicSharedMemorySize, SMEM_SZ);
    sphere_mma<<<(2 * HWSZ) / 128, 128, SMEM_SZ>>>(out);
}

// round 8
// speedup vs baseline: 2.7091x; 1.4631x over previous
#include <cuda_runtime.h>
#include <cuda_fp16.h>
#include <cstdint>

#define HT    256
#define WD    512
#define HWSZ  (HT*WD)          // 131072
#define CIN   64
#define COUT  64
#define KK2   9
#define KP    128              // K' = 128 (2-term fp16 split)
#define ROWB  256              // bytes per A/B row (KP * 2)

// ---------------- device scratch --------------------------------------------
__device__ float g_xhwc[2u * HT * WD * CIN];             // x in NHWC
__device__ __align__(16) uint16_t g_wB[KK2 * COUT * KP]; // fp16 B' [tap][n][128]
__device__ int4   g_off[KK2 * HWSZ];
__device__ float4 g_wt4[KK2 * HWSZ];

// ---------------- smem layout (bytes) ---------------------------------------
#define OFF_A   0
#define A_BYTES (128 * ROWB)          // 32768
#define OFF_B   A_BYTES               // two B buffers follow
#define B_BYTES (64 * ROWB)           // 16384
#define OFF_PO  (OFF_B + 2 * B_BYTES) // 65536
#define OFF_PW  (OFF_PO + 2048)
#define SMEM_SZ (OFF_PW + 2048)       // 69632

// 16B-chunk swizzle within groups of 8 chunks (row stride 256 = 0 mod 128)
__device__ __forceinline__ uint32_t swzc(uint32_t c, uint32_t r) {
    return (c & 8u) | ((c ^ r) & 7u);
}
__device__ __forceinline__ uint16_t f2h(float f) {
    uint16_t r; asm("cvt.rn.f16.f32 %0, %1;" : "=h"(r) : "f"(f)); return r;
}
__device__ __forceinline__ float h2f(uint16_t h) {
    float r; asm("cvt.f32.f16 %0, %1;" : "=f"(r) : "h"(h)); return r;
}
__device__ __forceinline__ uint32_t smem_u32(const void* p) {
    uint32_t a;
    asm("{ .reg .u64 t; cvta.to.shared.u64 t, %1; cvt.u32.u64 %0, t; }" : "=r"(a) : "l"(p));
    return a;
}
__device__ __forceinline__ void ldsm4(uint32_t r[4], uint32_t addr) {
    asm volatile("ldmatrix.sync.aligned.m8n8.x4.shared.b16 {%0,%1,%2,%3}, [%4];"
                 : "=r"(r[0]), "=r"(r[1]), "=r"(r[2]), "=r"(r[3]) : "r"(addr));
}
__device__ __forceinline__ void mma_f16(float c[4], const uint32_t a[4],
                                        const uint32_t b[2]) {
    asm volatile("mma.sync.aligned.m16n8k16.row.col.f32.f16.f16.f32 "
                 "{%0,%1,%2,%3}, {%4,%5,%6,%7}, {%8,%9}, {%0,%1,%2,%3};"
                 : "+f"(c[0]), "+f"(c[1]), "+f"(c[2]), "+f"(c[3])
                 : "r"(a[0]), "r"(a[1]), "r"(a[2]), "r"(a[3]), "r"(b[0]), "r"(b[1]));
}

// ---------------- prep: NCHW -> NHWC ----------------------------------------
__global__ void transpose_x(const float* __restrict__ x) {
    __shared__ float tile[32][33];
    const int w0 = blockIdx.x * 32, c0 = blockIdx.y * 32, nh = blockIdx.z;
    const int n = nh >> 8, h = nh & (HT - 1);
    const float* src = x + ((size_t)(n * CIN + c0)) * HWSZ + h * WD + w0;
#pragma unroll
    for (int i = 0; i < 32; i += 8)
        tile[threadIdx.y + i][threadIdx.x] = src[(size_t)(threadIdx.y + i) * HWSZ + threadIdx.x];
    __syncthreads();
    float* dst = g_xhwc + ((size_t)nh * WD + w0) * CIN + c0;
#pragma unroll
    for (int i = 0; i < 32; i += 8)
        dst[(size_t)(threadIdx.y + i) * CIN + threadIdx.x] = tile[threadIdx.x][threadIdx.y + i];
}

// ---------------- prep: weight fp16 duplicated layout ------------------------
// B'[n][2c] = B'[n][2c+1] = fp16(w[n][c])  (k even pairs with s_hi, odd with s_lo)
__global__ void weight_prep(const float* __restrict__ wgt) {
    int idx = blockIdx.x * 256 + threadIdx.x;    // tap*4096 + nn*64 + c
    if (idx >= KK2 * COUT * CIN) return;
    int c = idx & 63, rest = idx >> 6, nn = rest & 63, tap = rest >> 6;
    float wv = wgt[(nn * CIN + c) * KK2 + tap];
    uint16_t h = f2h(wv);
    uint16_t* dst = g_wB + ((size_t)tap * COUT + nn) * KP;
    dst[2 * c]     = h;
    dst[2 * c + 1] = h;
}

// ---------------- prep: bilinear offsets + weights --------------------------
__global__ void precomp(const float* __restrict__ pos) {
    int hw = blockIdx.x * 256 + threadIdx.x;
#pragma unroll 1
    for (int tap = 0; tap < KK2; tap++) {
        const float py = pos[(size_t)(2 * tap) * HWSZ + hw];
        const float px = pos[(size_t)(2 * tap + 1) * HWSZ + hw];
        const float y0f = floorf(py), x0f = floorf(px);
        const float dy = py - y0f, dx = px - x0f;
        const float y1f = y0f + 1.0f, x1f = x0f + 1.0f;
        const float vy0 = (y0f >= 0.0f && y0f <= (float)(HT - 1)) ? 1.0f : 0.0f;
        const float vy1 = (y1f >= 0.0f && y1f <= (float)(HT - 1)) ? 1.0f : 0.0f;
        const float vx0 = (x0f >= 0.0f && x0f <= (float)(WD - 1)) ? 1.0f : 0.0f;
        const float vx1 = (x1f >= 0.0f && x1f <= (float)(WD - 1)) ? 1.0f : 0.0f;
        float4 wt;
        wt.x = (1.0f - dy) * (1.0f - dx) * vy0 * vx0;
        wt.y = (1.0f - dy) * dx          * vy0 * vx1;
        wt.z = dy * (1.0f - dx)          * vy1 * vx0;
        wt.w = dy * dx                   * vy1 * vx1;
        const int yi0 = min(max((int)y0f, 0), HT - 1);
        const int yi1 = min(max((int)y1f, 0), HT - 1);
        const int xi0 = min(max((int)x0f, 0), WD - 1);
        const int xi1 = min(max((int)x1f, 0), WD - 1);
        int4 off;
        off.x = (yi0 * WD + xi0) * CIN;
        off.y = (yi0 * WD + xi1) * CIN;
        off.z = (yi1 * WD + xi0) * CIN;
        off.w = (yi1 * WD + xi1) * CIN;
        g_off[tap * HWSZ + hw] = off;
        g_wt4[tap * HWSZ + hw] = wt;
    }
}

// ---------------- main: gather + 2-term fp16 mma.sync GEMM ------------------
// block = 128 threads (4 warps), tile = 128 pixels x 64 couts, grid 2048
// warp w: gathers + owns pixels [w*32, w*32+32); mma M=32, N=64, K'=128
__global__ __launch_bounds__(128, 3)
void sphere_mma(float* __restrict__ out) {
    extern __shared__ char smem[];
    const uint32_t sb = smem_u32(smem);
    const int t = threadIdx.x, w = t >> 5, lane = t & 31;

    const int pixbase = blockIdx.x << 7;         // 128 pixels per block
    const int n   = pixbase >> 17;
    const int hwb = pixbase & (HWSZ - 1);
    const float* __restrict__ xb = g_xhwc + (size_t)n * (HWSZ * CIN);

    int4*   Po = (int4*)(smem + OFF_PO);
    float4* Pw = (float4*)(smem + OFF_PW);

    float acc[2][8][4];
#pragma unroll
    for (int mt = 0; mt < 2; mt++)
#pragma unroll
        for (int nt = 0; nt < 8; nt++)
#pragma unroll
            for (int j = 0; j < 4; j++) acc[mt][nt][j] = 0.0f;

    const uint32_t intra = (lane & 3) * 4;

    // ---- prologue: stage B(0) into buffer 0 (8 x 16B chunks per thread) ----
    {
        const char* wsrc = (const char*)g_wB;
#pragma unroll
        for (int i = 0; i < 8; i++) {
            int id  = t + (i << 7);              // 0..1023
            int row = id >> 4, c = id & 15;
            uint4 v = *(const uint4*)(wsrc + row * ROWB + c * 16);
            *(uint4*)(smem + OFF_B + row * ROWB + swzc(c, row) * 16) = v;
        }
    }
    __syncthreads();

#pragma unroll 1
    for (int tap = 0; tap < KK2; tap++) {
        // ---- stage B(tap+1) into alternate buffer (overlaps with gather/mma) ----
        if (tap < KK2 - 1) {
            const char* wsrc = (const char*)(g_wB + (size_t)(tap + 1) * COUT * KP);
            char* bdst = smem + OFF_B + ((tap + 1) & 1) * B_BYTES;
#pragma unroll
            for (int i = 0; i < 8; i++) {
                int id  = t + (i << 7);
                int row = id >> 4, c = id & 15;
                uint4 v = *(const uint4*)(wsrc + row * ROWB + c * 16);
                *(uint4*)(bdst + row * ROWB + swzc(c, row) * 16) = v;
            }
        }

        // ---- stage this warp's Po/Pw (warp-private region) ----
        Po[w * 32 + lane] = g_off[tap * HWSZ + hwb + w * 32 + lane];
        Pw[w * 32 + lane] = g_wt4[tap * HWSZ + hwb + w * 32 + lane];
        __syncwarp();

        // ---- gather own 32 pixels: lane = channel (ci=lane, lane+32) ----
        const float* bp0 = xb + lane;
        const float* bp1 = xb + 32 + lane;
#pragma unroll 2
        for (int g = 0; g < 8; g++) {
            const int p0 = w * 32 + g * 4;
            int4   o[4];
            float4 q[4];
#pragma unroll
            for (int j = 0; j < 4; j++) { o[j] = Po[p0 + j]; q[j] = Pw[p0 + j]; }

            float A0[4][4], A1[4][4];
#pragma unroll
            for (int j = 0; j < 4; j++) {
                A0[j][0] = bp0[o[j].x]; A0[j][1] = bp0[o[j].y];
                A0[j][2] = bp0[o[j].z]; A0[j][3] = bp0[o[j].w];
                A1[j][0] = bp1[o[j].x]; A1[j][1] = bp1[o[j].y];
                A1[j][2] = bp1[o[j].z]; A1[j][3] = bp1[o[j].w];
            }
#pragma unroll
            for (int j = 0; j < 4; j++) {
                const int pl = p0 + j;
                const uint32_t rb = (uint32_t)pl * ROWB;
                float s0 = fmaf(q[j].x, A0[j][0], fmaf(q[j].y, A0[j][1],
                          fmaf(q[j].z, A0[j][2], q[j].w * A0[j][3])));
                float s1 = fmaf(q[j].x, A1[j][0], fmaf(q[j].y, A1[j][1],
                          fmaf(q[j].z, A1[j][2], q[j].w * A1[j][3])));
                uint16_t h0 = f2h(s0);
                uint16_t l0 = f2h(s0 - h2f(h0));
                uint16_t h1 = f2h(s1);
                uint16_t l1 = f2h(s1 - h2f(h1));
                uint32_t pr0 = (uint32_t)h0 | ((uint32_t)l0 << 16);
                uint32_t pr1 = (uint32_t)h1 | ((uint32_t)l1 << 16);
                // ci = lane   -> k bytes [4*lane]     -> chunk lane>>2
                // ci = lane+32-> k bytes [128+4*lane] -> chunk 8+(lane>>2)
                *(uint32_t*)(smem + rb + swzc(lane >> 2, pl) * 16 + intra)       = pr0;
                *(uint32_t*)(smem + rb + swzc(8 + (lane >> 2), pl) * 16 + intra) = pr1;
            }
        }
        __syncwarp();

        // ---- mma: M=32 (own rows), N=64, K'=128 from B buffer tap&1 ----
        const uint32_t abase = sb + OFF_A;
        const uint32_t bbase = sb + OFF_B + (tap & 1) * B_BYTES;
#pragma unroll 4
        for (int kc = 0; kc < 8; kc++) {
            uint32_t a[2][4];
#pragma unroll
            for (int mt = 0; mt < 2; mt++) {
                uint32_t row = (uint32_t)(w * 32 + mt * 16 + (lane & 15));
                uint32_t kch = (uint32_t)(kc * 2 + (lane >> 4));
                ldsm4(a[mt], abase + row * ROWB + swzc(kch, row) * 16);
            }
            uint32_t b[8][2];
#pragma unroll
            for (int np = 0; np < 4; np++) {
                uint32_t nr  = (uint32_t)(np * 16 + (lane & 7) + ((lane >> 4) << 3));
                uint32_t kch = (uint32_t)(kc * 2 + ((lane >> 3) & 1));
                uint32_t r[4];
                ldsm4(r, bbase + nr * ROWB + swzc(kch, nr) * 16);
                b[2 * np][0]     = r[0]; b[2 * np][1]     = r[1];
                b[2 * np + 1][0] = r[2]; b[2 * np + 1][1] = r[3];
            }
#pragma unroll
            for (int mt = 0; mt < 2; mt++)
#pragma unroll
                for (int nt = 0; nt < 8; nt++)
                    mma_f16(acc[mt][nt], a[mt], b[nt]);
        }
        __syncthreads();   // all warps done with B(tap) and this tap's staging
    }

    // ---- epilogue ----------------------------------------------------------
    float* ob = out + (size_t)n * COUT * HWSZ + hwb;
#pragma unroll
    for (int mt = 0; mt < 2; mt++) {
        const int pl = w * 32 + mt * 16 + (lane >> 2);
#pragma unroll
        for (int nt = 0; nt < 8; nt++) {
            const int co = nt * 8 + (lane & 3) * 2;
            ob[(size_t)co * HWSZ + pl]           = acc[mt][nt][0];
            ob[(size_t)(co + 1) * HWSZ + pl]     = acc[mt][nt][1];
            ob[(size_t)co * HWSZ + pl + 8]       = acc[mt][nt][2];
            ob[(size_t)(co + 1) * HWSZ + pl + 8] = acc[mt][nt][3];
        }
    }
}

// ---------------- launch ----------------------------------------------------
extern "C" void kernel_launch(void* const* d_in, const int* in_sizes, int n_in,
                              void* d_out, int out_size) {
    const float* x   = (const float*)d_in[0];
    const float* wgt = (const float*)d_in[1];
    const float* pos = (const float*)d_in[2];
    float* out = (float*)d_out;

    transpose_x<<<dim3(WD / 32, CIN / 32, 2 * HT), dim3(32, 8)>>>(x);
    weight_prep<<<(KK2 * COUT * CIN + 255) / 256, 256>>>(wgt);
    precomp<<<HWSZ / 256, 256>>>(pos);

    cudaFuncSetAttribute(sphere_mma, cudaFuncAttributeMaxDynamicSharedMemorySize, SMEM_SZ);
    sphere_mma<<<(2 * HWSZ) / 128, 128, SMEM_SZ>>>(out);
}

// round 9
// speedup vs baseline: 3.9147x; 1.4450x over previous
#include <cuda_runtime.h>
#include <cuda_fp16.h>
#include <cstdint>

#define HT    256
#define WD    512
#define HWSZ  (HT*WD)          // 131072
#define CIN   64
#define COUT  64
#define KK2   9
#define KP    64               // K' = 64 (plain fp16 GEMM)
#define ROWB  128              // bytes per A/B row (KP * 2)

// ---------------- device scratch --------------------------------------------
__device__ __align__(16) uint16_t g_x16[2u * HT * WD * CIN];   // x in NHWC fp16
__device__ __align__(16) uint16_t g_wB[KK2 * COUT * KP];       // fp16 B [tap][n][64]
__device__ int4   g_off[KK2 * HWSZ];
__device__ float4 g_wt4[KK2 * HWSZ];

// ---------------- smem layout (bytes) ---------------------------------------
#define OFF_A   0
#define A_BYTES (128 * ROWB)          // 16384
#define OFF_B   A_BYTES               // two B buffers follow
#define B_BYTES (64 * ROWB)           // 8192
#define OFF_PO  (OFF_B + 2 * B_BYTES) // 32768
#define OFF_PW  (OFF_PO + 2048)
#define SMEM_SZ (OFF_PW + 2048)       // 36864

// 16B-chunk swizzle within a 128B row (8 chunks)
__device__ __forceinline__ uint32_t swzc(uint32_t c, uint32_t r) {
    return (c & ~7u) | ((c ^ r) & 7u);
}
__device__ __forceinline__ uint16_t f2h(float f) {
    uint16_t r; asm("cvt.rn.f16.f32 %0, %1;" : "=h"(r) : "f"(f)); return r;
}
__device__ __forceinline__ float2 h2f2(uint32_t v) {
    float2 r;
    asm("{.reg .f16 lo,hi; mov.b32 {lo,hi}, %2; cvt.f32.f16 %0, lo; cvt.f32.f16 %1, hi;}"
        : "=f"(r.x), "=f"(r.y) : "r"(v));
    return r;
}
__device__ __forceinline__ uint32_t f2h2(float lo, float hi) {
    uint32_t r;
    asm("cvt.rn.f16x2.f32 %0, %1, %2;" : "=r"(r) : "f"(hi), "f"(lo));
    return r;
}
__device__ __forceinline__ uint32_t smem_u32(const void* p) {
    uint32_t a;
    asm("{ .reg .u64 t; cvta.to.shared.u64 t, %1; cvt.u32.u64 %0, t; }" : "=r"(a) : "l"(p));
    return a;
}
__device__ __forceinline__ void ldsm4(uint32_t r[4], uint32_t addr) {
    asm volatile("ldmatrix.sync.aligned.m8n8.x4.shared.b16 {%0,%1,%2,%3}, [%4];"
                 : "=r"(r[0]), "=r"(r[1]), "=r"(r[2]), "=r"(r[3]) : "r"(addr));
}
__device__ __forceinline__ void mma_f16(float c[4], const uint32_t a[4],
                                        const uint32_t b[2]) {
    asm volatile("mma.sync.aligned.m16n8k16.row.col.f32.f16.f16.f32 "
                 "{%0,%1,%2,%3}, {%4,%5,%6,%7}, {%8,%9}, {%0,%1,%2,%3};"
                 : "+f"(c[0]), "+f"(c[1]), "+f"(c[2]), "+f"(c[3])
                 : "r"(a[0]), "r"(a[1]), "r"(a[2]), "r"(a[3]), "r"(b[0]), "r"(b[1]));
}

// ---------------- prep: NCHW fp32 -> NHWC fp16 -------------------------------
__global__ void transpose_x(const float* __restrict__ x) {
    __shared__ float tile[32][33];
    const int w0 = blockIdx.x * 32, c0 = blockIdx.y * 32, nh = blockIdx.z;
    const int n = nh >> 8, h = nh & (HT - 1);
    const float* src = x + ((size_t)(n * CIN + c0)) * HWSZ + h * WD + w0;
#pragma unroll
    for (int i = 0; i < 32; i += 8)
        tile[threadIdx.y + i][threadIdx.x] = src[(size_t)(threadIdx.y + i) * HWSZ + threadIdx.x];
    __syncthreads();
    uint16_t* dst = g_x16 + ((size_t)nh * WD + w0) * CIN + c0;
#pragma unroll
    for (int i = 0; i < 32; i += 8)
        dst[(size_t)(threadIdx.y + i) * CIN + threadIdx.x] =
            f2h(tile[threadIdx.x][threadIdx.y + i]);
}

// ---------------- prep: weight fp16 [tap][n][c] ------------------------------
__global__ void weight_prep(const float* __restrict__ wgt) {
    int idx = blockIdx.x * 256 + threadIdx.x;    // tap*4096 + nn*64 + c
    if (idx >= KK2 * COUT * CIN) return;
    int c = idx & 63, rest = idx >> 6, nn = rest & 63, tap = rest >> 6;
    g_wB[idx] = f2h(wgt[(nn * CIN + c) * KK2 + tap]);
}

// ---------------- prep: bilinear offsets + weights --------------------------
__global__ void precomp(const float* __restrict__ pos) {
    int hw = blockIdx.x * 256 + threadIdx.x;
#pragma unroll 1
    for (int tap = 0; tap < KK2; tap++) {
        const float py = pos[(size_t)(2 * tap) * HWSZ + hw];
        const float px = pos[(size_t)(2 * tap + 1) * HWSZ + hw];
        const float y0f = floorf(py), x0f = floorf(px);
        const float dy = py - y0f, dx = px - x0f;
        const float y1f = y0f + 1.0f, x1f = x0f + 1.0f;
        const float vy0 = (y0f >= 0.0f && y0f <= (float)(HT - 1)) ? 1.0f : 0.0f;
        const float vy1 = (y1f >= 0.0f && y1f <= (float)(HT - 1)) ? 1.0f : 0.0f;
        const float vx0 = (x0f >= 0.0f && x0f <= (float)(WD - 1)) ? 1.0f : 0.0f;
        const float vx1 = (x1f >= 0.0f && x1f <= (float)(WD - 1)) ? 1.0f : 0.0f;
        float4 wt;
        wt.x = (1.0f - dy) * (1.0f - dx) * vy0 * vx0;
        wt.y = (1.0f - dy) * dx          * vy0 * vx1;
        wt.z = dy * (1.0f - dx)          * vy1 * vx0;
        wt.w = dy * dx                   * vy1 * vx1;
        const int yi0 = min(max((int)y0f, 0), HT - 1);
        const int yi1 = min(max((int)y1f, 0), HT - 1);
        const int xi0 = min(max((int)x0f, 0), WD - 1);
        const int xi1 = min(max((int)x1f, 0), WD - 1);
        int4 off;   // byte offsets into fp16 NHWC
        off.x = (yi0 * WD + xi0) * CIN * 2;
        off.y = (yi0 * WD + xi1) * CIN * 2;
        off.z = (yi1 * WD + xi0) * CIN * 2;
        off.w = (yi1 * WD + xi1) * CIN * 2;
        g_off[tap * HWSZ + hw] = off;
        g_wt4[tap * HWSZ + hw] = wt;
    }
}

// ---------------- main: fp16 gather + fp16 mma.sync GEMM --------------------
// block = 128 threads (4 warps), tile = 128 pixels x 64 couts, grid 2048
// warp w: gathers + owns pixels [w*32, w*32+32); mma M=32, N=64, K'=64
// gather lane l holds channels (2l, 2l+1) packed fp16x2
__global__ __launch_bounds__(128, 3)
void sphere_mma(float* __restrict__ out) {
    extern __shared__ char smem[];
    const uint32_t sb = smem_u32(smem);
    const int t = threadIdx.x, w = t >> 5, lane = t & 31;

    const int pixbase = blockIdx.x << 7;         // 128 pixels per block
    const int n   = pixbase >> 17;
    const int hwb = pixbase & (HWSZ - 1);
    const char* __restrict__ xb = (const char*)(g_x16 + (size_t)n * (HWSZ * CIN));

    int4*   Po = (int4*)(smem + OFF_PO);
    float4* Pw = (float4*)(smem + OFF_PW);

    float acc[2][8][4];
#pragma unroll
    for (int mt = 0; mt < 2; mt++)
#pragma unroll
        for (int nt = 0; nt < 8; nt++)
#pragma unroll
            for (int j = 0; j < 4; j++) acc[mt][nt][j] = 0.0f;

    const uint32_t lb = lane * 4;                // byte offset of channels (2l,2l+1)
    const uint32_t intra = (lane & 3) * 4;

    // ---- prologue: stage B(0) into buffer 0 (4 x 16B chunks per thread) ----
    {
        const char* wsrc = (const char*)g_wB;
#pragma unroll
        for (int i = 0; i < 4; i++) {
            int id  = t + (i << 7);              // 0..511
            int row = id >> 3, c = id & 7;
            uint4 v = *(const uint4*)(wsrc + row * ROWB + c * 16);
            *(uint4*)(smem + OFF_B + row * ROWB + swzc(c, row) * 16) = v;
        }
    }
    __syncthreads();

#pragma unroll 1
    for (int tap = 0; tap < KK2; tap++) {
        // ---- stage B(tap+1) into alternate buffer ----
        if (tap < KK2 - 1) {
            const char* wsrc = (const char*)(g_wB + (size_t)(tap + 1) * COUT * KP);
            char* bdst = smem + OFF_B + ((tap + 1) & 1) * B_BYTES;
#pragma unroll
            for (int i = 0; i < 4; i++) {
                int id  = t + (i << 7);
                int row = id >> 3, c = id & 7;
                uint4 v = *(const uint4*)(wsrc + row * ROWB + c * 16);
                *(uint4*)(bdst + row * ROWB + swzc(c, row) * 16) = v;
            }
        }

        // ---- stage this warp's Po/Pw (warp-private region) ----
        Po[w * 32 + lane] = g_off[tap * HWSZ + hwb + w * 32 + lane];
        Pw[w * 32 + lane] = g_wt4[tap * HWSZ + hwb + w * 32 + lane];
        __syncwarp();

        // ---- gather own 32 pixels: 4 corner u32 loads, 1 STS per pixel ----
#pragma unroll 2
        for (int g = 0; g < 8; g++) {
            const int p0 = w * 32 + g * 4;
            int4   o[4];
            float4 q[4];
#pragma unroll
            for (int j = 0; j < 4; j++) { o[j] = Po[p0 + j]; q[j] = Pw[p0 + j]; }

            uint32_t C[4][4];
#pragma unroll
            for (int j = 0; j < 4; j++) {
                C[j][0] = *(const uint32_t*)(xb + o[j].x + lb);
                C[j][1] = *(const uint32_t*)(xb + o[j].y + lb);
                C[j][2] = *(const uint32_t*)(xb + o[j].z + lb);
                C[j][3] = *(const uint32_t*)(xb + o[j].w + lb);
            }
#pragma unroll
            for (int j = 0; j < 4; j++) {
                const int pl = p0 + j;
                float2 u0 = h2f2(C[j][0]);
                float2 u1 = h2f2(C[j][1]);
                float2 u2 = h2f2(C[j][2]);
                float2 u3 = h2f2(C[j][3]);
                float se = fmaf(q[j].x, u0.x, fmaf(q[j].y, u1.x,
                          fmaf(q[j].z, u2.x, q[j].w * u3.x)));
                float so = fmaf(q[j].x, u0.y, fmaf(q[j].y, u1.y,
                          fmaf(q[j].z, u2.y, q[j].w * u3.y)));
                // channels (2l, 2l+1) -> row bytes [4l, 4l+4) -> chunk l>>2
                *(uint32_t*)(smem + (uint32_t)pl * ROWB +
                             swzc(lane >> 2, pl) * 16 + intra) = f2h2(se, so);
            }
        }
        __syncwarp();

        // ---- mma: M=32 (own rows), N=64, K'=64 from B buffer tap&1 ----
        const uint32_t abase = sb + OFF_A;
        const uint32_t bbase = sb + OFF_B + (tap & 1) * B_BYTES;
#pragma unroll
        for (int kc = 0; kc < 4; kc++) {
            uint32_t a[2][4];
#pragma unroll
            for (int mt = 0; mt < 2; mt++) {
                uint32_t row = (uint32_t)(w * 32 + mt * 16 + (lane & 15));
                uint32_t kch = (uint32_t)(kc * 2 + (lane >> 4));
                ldsm4(a[mt], abase + row * ROWB + swzc(kch, row) * 16);
            }
            uint32_t b[8][2];
#pragma unroll
            for (int np = 0; np < 4; np++) {
                uint32_t nr  = (uint32_t)(np * 16 + (lane & 7) + ((lane >> 4) << 3));
                uint32_t kch = (uint32_t)(kc * 2 + ((lane >> 3) & 1));
                uint32_t r[4];
                ldsm4(r, bbase + nr * ROWB + swzc(kch, nr) * 16);
                b[2 * np][0]     = r[0]; b[2 * np][1]     = r[1];
                b[2 * np + 1][0] = r[2]; b[2 * np + 1][1] = r[3];
            }
#pragma unroll
            for (int mt = 0; mt < 2; mt++)
#pragma unroll
                for (int nt = 0; nt < 8; nt++)
                    mma_f16(acc[mt][nt], a[mt], b[nt]);
        }
        __syncthreads();   // all warps done with B(tap) before its re-stage
    }

    // ---- epilogue ----------------------------------------------------------
    float* ob = out + (size_t)n * COUT * HWSZ + hwb;
#pragma unroll
    for (int mt = 0; mt < 2; mt++) {
        const int pl = w * 32 + mt * 16 + (lane >> 2);
#pragma unroll
        for (int nt = 0; nt < 8; nt++) {
            const int co = nt * 8 + (lane & 3) * 2;
            ob[(size_t)co * HWSZ + pl]           = acc[mt][nt][0];
            ob[(size_t)(co + 1) * HWSZ + pl]     = acc[mt][nt][1];
            ob[(size_t)co * HWSZ + pl + 8]       = acc[mt][nt][2];
            ob[(size_t)(co + 1) * HWSZ + pl + 8] = acc[mt][nt][3];
        }
    }
}

// ---------------- launch ----------------------------------------------------
extern "C" void kernel_launch(void* const* d_in, const int* in_sizes, int n_in,
                              void* d_out, int out_size) {
    const float* x   = (const float*)d_in[0];
    const float* wgt = (const float*)d_in[1];
    const float* pos = (const float*)d_in[2];
    float* out = (float*)d_out;

    transpose_x<<<dim3(WD / 32, CIN / 32, 2 * HT), dim3(32, 8)>>>(x);
    weight_prep<<<(KK2 * COUT * CIN + 255) / 256, 256>>>(wgt);
    precomp<<<HWSZ / 256, 256>>>(pos);

    cudaFuncSetAttribute(sphere_mma, cudaFuncAttributeMaxDynamicSharedMemorySize, SMEM_SZ);
    sphere_mma<<<(2 * HWSZ) / 128, 128, SMEM_SZ>>>(out);
}